// round 3
// baseline (speedup 1.0000x reference)
#include <cuda_runtime.h>
#include <cstdint>

// LSTMCell fused: z = [x|h] @ Wp + bp ; gates -> C_new, h_new
// GEMM [32768 x 1024] * [1024 x 2048] via mma.sync tf32 m16n8k8.
// Key change vs R1: fragment-linear smem layouts -> LDS.128/LDS.64 fragment
// loads (8 vector LDS per warp-k8 instead of 24 scalar LDS).

#define NB    32768
#define DH    512
#define FOURH 2048
#define KTOT  1024
#define NKB   64          // KTOT / BK

#define BM 128
#define BN 128
#define BK 16
#define EST 132           // epilogue smem stride
// mainloop smem: A 2 buf x 2048 floats, B 2 buf x 2048 floats = 8192
// epilogue: 64 rows x EST = 8448 floats
#define SMEM_FLOATS 8448
#define B_OFF 4096

__device__ float g_Wp[(size_t)FOURH * KTOT]; // fragment-linear tiled B^T (see prep)
__device__ float g_bp[FOURH];                // combined gate-interleaved bias

__device__ __forceinline__ float tf32r(float x) {
    float r; asm("cvt.rna.tf32.f32 %0, %1;" : "=f"(r) : "f"(x)); return r;
}
__device__ __forceinline__ float tanh_fast(float x) {
    float r; asm("tanh.approx.f32 %0, %1;" : "=f"(r) : "f"(x)); return r;
}
__device__ __forceinline__ float sig_fast(float x) { return 0.5f * tanh_fast(0.5f * x) + 0.5f; }

// ---------------- prep ----------------
// B^T element (n, k):  n gate-interleaved (j = n>>2, g = n&3), value tf32-rounded.
// Stored fragment-linear: tile (kb = k>>3, nb = n>>3) of 64 floats at
//   ((kb*256 + nb)*64) + (n_in*4 + (k_in&3))*2 + (k_in>>2)
// so thread lane of a warp reads {b0,b1} as one contiguous LDS.64.
__global__ void prep_kernel(const float* __restrict__ Wx, const float* __restrict__ Wh,
                            const float* __restrict__ bx, const float* __restrict__ bh) {
    int idx = blockIdx.x * 256 + threadIdx.x;
    if (idx < FOURH * KTOT) {
        int kb   = idx >> 14;          // 0..127
        int nb   = (idx >> 6) & 255;   // 0..255
        int pos  = idx & 63;
        int jbit = pos & 1;            // k_in >> 2
        int t    = pos >> 1;
        int n_in = t >> 2;
        int k_in = (t & 3) | (jbit << 2);
        int n = nb * 8 + n_in;
        int k = kb * 8 + k_in;
        int j = n >> 2, g = n & 3;
        float v = (k < DH) ? Wx[k * FOURH + g * DH + j]
                           : Wh[(k - DH) * FOURH + g * DH + j];
        g_Wp[idx] = tf32r(v);
    }
    if (idx < FOURH) {
        int j = idx >> 2, g = idx & 3;
        g_bp[idx] = bx[g * DH + j] + bh[g * DH + j];
    }
}

// ---------------- main kernel ----------------
__global__ void __launch_bounds__(256, 2)
lstm_kernel(const float* __restrict__ x, const float* __restrict__ h,
            const float* __restrict__ Cin, float* __restrict__ out) {
    __shared__ float smem[SMEM_FLOATS];

    const int tid    = threadIdx.x;
    const int lane   = tid & 31;
    const int wid    = tid >> 5;
    const int warp_m = wid & 1;    // 0..1 : 64-row halves
    const int warp_n = wid >> 1;   // 0..3 : 32-col slices
    const int m0 = blockIdx.y * BM;
    const int n0 = blockIdx.x * BN;

    float acc[4][4][4];
#pragma unroll
    for (int a = 0; a < 4; a++)
#pragma unroll
        for (int b = 0; b < 4; b++)
#pragma unroll
            for (int c = 0; c < 4; c++) acc[a][b][c] = 0.f;

    // ---- A staging geometry (fragment-linear) ----
    // tile = tid>>4 (= ks*8 + mi), tsub = tid&15 handles fragments t=2*tsub, 2*tsub+1
    const int a_tile = tid >> 4;
    const int a_ks   = a_tile >> 3;       // 0..1
    const int a_mi   = a_tile & 7;        // 0..7
    const int tsub   = tid & 15;
    const int a_r0   = tsub >> 1;         // row within 16-tile (and +8)
    const int a_cc   = 2 * (tsub & 1);    // col within 8-wide k-slice
    const int a_rowg = a_mi * 16 + a_r0;  // + m0

    float2 aD[4];
    float4 bD[2];

    auto LOADG = [&](int kb) {
        const float* Ap = (kb < 32) ? x : h;
        const float* ar = Ap + (size_t)(m0 + a_rowg) * DH + (kb & 31) * BK + a_ks * 8 + a_cc;
        aD[0] = *(const float2*)&ar[0];
        aD[1] = *(const float2*)&ar[4];
        aD[2] = *(const float2*)&ar[8 * DH];
        aD[3] = *(const float2*)&ar[8 * DH + 4];
        const float* br = g_Wp + (size_t)(kb * 2 + (tid >> 7)) * 16384
                               + (size_t)blockIdx.x * 1024 + ((tid * 8) & 1023);
        bD[0] = *(const float4*)&br[0];
        bD[1] = *(const float4*)&br[4];
    };

    auto STORES = [&](int buf) {
        float* A = smem + buf * 2048 + a_tile * 128 + tsub * 8;
        *(float4*)&A[0] = make_float4(tf32r(aD[0].x), tf32r(aD[2].x),
                                      tf32r(aD[1].x), tf32r(aD[3].x));
        *(float4*)&A[4] = make_float4(tf32r(aD[0].y), tf32r(aD[2].y),
                                      tf32r(aD[1].y), tf32r(aD[3].y));
        float* Bm = smem + B_OFF + buf * 2048 + tid * 8;
        *(float4*)&Bm[0] = bD[0];
        *(float4*)&Bm[4] = bD[1];
    };

    auto COMPUTE = [&](int buf) {
        const float* A  = smem + buf * 2048;
        const float* Bm = smem + B_OFF + buf * 2048;
#pragma unroll
        for (int ks = 0; ks < 2; ks++) {
            uint4 af[4];
            uint2 bf[4];
#pragma unroll
            for (int mi = 0; mi < 4; mi++)
                af[mi] = *(const uint4*)&A[(ks * 8 + warp_m * 4 + mi) * 128 + lane * 4];
#pragma unroll
            for (int ni = 0; ni < 4; ni++)
                bf[ni] = *(const uint2*)&Bm[ks * 1024 + (warp_n * 4 + ni) * 64 + lane * 2];
#pragma unroll
            for (int mi = 0; mi < 4; mi++)
#pragma unroll
                for (int ni = 0; ni < 4; ni++)
                    asm volatile(
                        "mma.sync.aligned.m16n8k8.row.col.f32.tf32.tf32.f32 "
                        "{%0,%1,%2,%3},{%4,%5,%6,%7},{%8,%9},{%0,%1,%2,%3};"
                        : "+f"(acc[mi][ni][0]), "+f"(acc[mi][ni][1]),
                          "+f"(acc[mi][ni][2]), "+f"(acc[mi][ni][3])
                        : "r"(af[mi].x), "r"(af[mi].y), "r"(af[mi].z), "r"(af[mi].w),
                          "r"(bf[ni].x), "r"(bf[ni].y));
        }
    };

    // ---- mainloop: double-buffered ----
    LOADG(0);
    STORES(0);
    __syncthreads();
#pragma unroll 1
    for (int kb = 0; kb < NKB; kb++) {
        if (kb + 1 < NKB) LOADG(kb + 1);
        COMPUTE(kb & 1);
        __syncthreads();
        if (kb + 1 < NKB) {
            STORES((kb + 1) & 1);
            __syncthreads();
        }
    }

    // ---- fused epilogue: gates are adjacent columns (4j..4j+3) ----
    const int jl  = tid & 31;
    const int hid = (n0 >> 2) + jl;
    const float4 bias = *(const float4*)&g_bp[n0 + 4 * jl];

#pragma unroll
    for (int p = 0; p < 2; p++) {
        __syncthreads();
        if (warp_m == p) {
#pragma unroll
            for (int mi = 0; mi < 4; mi++)
#pragma unroll
                for (int ni = 0; ni < 4; ni++) {
                    int rl = mi * 16 + (lane >> 2);
                    int c  = warp_n * 32 + ni * 8 + 2 * (lane & 3);
                    smem[rl * EST + c]           = acc[mi][ni][0];
                    smem[rl * EST + c + 1]       = acc[mi][ni][1];
                    smem[(rl + 8) * EST + c]     = acc[mi][ni][2];
                    smem[(rl + 8) * EST + c + 1] = acc[mi][ni][3];
                }
        }
        __syncthreads();
#pragma unroll
        for (int it = 0; it < 8; it++) {
            int rl  = (tid >> 5) + 8 * it;
            int row = m0 + p * 64 + rl;
            float4 z = *(const float4*)&smem[rl * EST + 4 * jl];
            float iv = sig_fast(z.x + bias.x);
            float fv = sig_fast(z.y + bias.y);
            float ov = sig_fast(z.z + bias.z);
            float gv = tanh_fast(z.w + bias.w);
            float Cn = fv * Cin[(size_t)row * DH + hid] + iv * gv;
            float hn = ov * tanh_fast(Cn);
            out[(size_t)row * DH + hid]                   = Cn;
            out[(size_t)NB * DH + (size_t)row * DH + hid] = hn;
        }
    }
}

extern "C" void kernel_launch(void* const* d_in, const int* in_sizes, int n_in,
                              void* d_out, int out_size) {
    const float* x  = (const float*)d_in[0];
    const float* C  = (const float*)d_in[1];
    const float* h  = (const float*)d_in[2];
    const float* Wx = (const float*)d_in[3];
    const float* bx = (const float*)d_in[4];
    const float* Wh = (const float*)d_in[5];
    const float* bh = (const float*)d_in[6];

    prep_kernel<<<(FOURH * KTOT + 255) / 256, 256>>>(Wx, Wh, bx, bh);

    dim3 grid(FOURH / BN, NB / BM);  // (16, 256) — x-fastest keeps A tile hot in L2
    lstm_kernel<<<grid, 256>>>(x, h, C, (float*)d_out);
}

// round 5
// speedup vs baseline: 1.0073x; 1.0073x over previous
#include <cuda_runtime.h>
#include <cstdint>

// LSTMCell fused: z = [x|h] @ Wp + bp ; gates -> C_new, h_new
// GEMM [32768 x 1024] * [1024 x 2048], mma.sync tf32 m16n8k8.
// R4: warp tile 64x64 (halves smem operand bytes/FLOP), cp.async 4-stage
// pipeline with one sync per k-tile, register accumulators, single-pass
// fused gate epilogue.

#define NB    32768
#define DH    512
#define FOURH 2048
#define KTOT  1024
#define NKB   64          // KTOT / BK

#define BM 128
#define BN 256
#define BK 16
#define STAGES 4

#define AROWSTRIDE 36                       // floats; 144B rows (16B aligned), conflict-free
#define A_STAGE_FLOATS (BM * AROWSTRIDE)    // 4608
#define B_STAGE_FLOATS (BN * BK)            // 4096
#define STAGE_FLOATS   (A_STAGE_FLOATS + B_STAGE_FLOATS)  // 8704
#define DYN_SMEM       (STAGES * STAGE_FLOATS * 4)        // 139264 B
#define EST 264                             // epilogue stride: 128*264 = 33792 <= 4*8704

__device__ float g_Wp[(size_t)FOURH * KTOT]; // fragment-linear tiled B^T (R3 format, validated)
__device__ float g_bp[FOURH];                // combined gate-interleaved bias

__device__ __forceinline__ float tf32r(float x) {
    float r; asm("cvt.rna.tf32.f32 %0, %1;" : "=f"(r) : "f"(x)); return r;
}
__device__ __forceinline__ float tanh_fast(float x) {
    float r; asm("tanh.approx.f32 %0, %1;" : "=f"(r) : "f"(x)); return r;
}
__device__ __forceinline__ float sig_fast(float x) { return 0.5f * tanh_fast(0.5f * x) + 0.5f; }

__device__ __forceinline__ void cp16(uint32_t dst, const float* src) {
    asm volatile("cp.async.cg.shared.global [%0], [%1], 16;" :: "r"(dst), "l"(src));
}
__device__ __forceinline__ void cp_commit() { asm volatile("cp.async.commit_group;" ::: "memory"); }
template <int N> __device__ __forceinline__ void cp_wait() {
    asm volatile("cp.async.wait_group %0;" :: "n"(N) : "memory");
}
__device__ __forceinline__ uint32_t smem_u32(const void* p) {
    uint32_t a;
    asm("{ .reg .u64 t; cvta.to.shared.u64 t, %1; cvt.u32.u64 %0, t; }" : "=r"(a) : "l"(p));
    return a;
}

// ---------------- prep (unchanged from R3, validated) ----------------
// B^T element (n, k): n gate-interleaved (j=n>>2, g=n&3), tf32-RNA rounded.
// Fragment-linear: tile (kb8=k>>3, nb=n>>3) of 64 floats at
//   ((kb8*256 + nb)*64) + (n_in*4 + (k_in&3))*2 + (k_in>>2)
__global__ void prep_kernel(const float* __restrict__ Wx, const float* __restrict__ Wh,
                            const float* __restrict__ bx, const float* __restrict__ bh) {
    int idx = blockIdx.x * 256 + threadIdx.x;
    if (idx < FOURH * KTOT) {
        int kb8  = idx >> 14;
        int nb   = (idx >> 6) & 255;
        int pos  = idx & 63;
        int jbit = pos & 1;
        int t    = pos >> 1;
        int n_in = t >> 2;
        int k_in = (t & 3) | (jbit << 2);
        int n = nb * 8 + n_in;
        int k = kb8 * 8 + k_in;
        int j = n >> 2, g = n & 3;
        float v = (k < DH) ? Wx[k * FOURH + g * DH + j]
                           : Wh[(k - DH) * FOURH + g * DH + j];
        g_Wp[idx] = tf32r(v);
    }
    if (idx < FOURH) {
        int j = idx >> 2, g = idx & 3;
        g_bp[idx] = bx[g * DH + j] + bh[g * DH + j];
    }
}

// ---------------- main kernel ----------------
__global__ void __launch_bounds__(256, 1)
lstm_kernel(const float* __restrict__ x, const float* __restrict__ h,
            const float* __restrict__ Cin, float* __restrict__ out) {
    extern __shared__ float smem[];

    const int tid    = threadIdx.x;
    const int lane   = tid & 31;
    const int wid    = tid >> 5;
    const int warp_m = wid & 1;    // 0..1 : 64-row halves
    const int warp_n = wid >> 1;   // 0..3 : 64-col slices
    const int m0 = blockIdx.y * BM;
    const int n0 = blockIdx.x * BN;

    float acc[4][8][4];
#pragma unroll
    for (int a = 0; a < 4; a++)
#pragma unroll
        for (int b = 0; b < 8; b++)
#pragma unroll
            for (int c = 0; c < 4; c++) acc[a][b][c] = 0.f;

    const uint32_t sbase = smem_u32(smem);

    // ---- fill geometry ----
    // A: 512 16B-chunks; thread does ids {2tid, 2tid+1}: row=id>>2, c16=id&3
    const int a_row = tid >> 1;
    const int a_c0  = (tid & 1) * 2;      // c16 of first chunk
    // B: thread copies floats [tid*16 .. +15] of the 4096-float stage
    const int b_ks  = tid >> 7;           // 0..1
    const size_t b_goff = (size_t)blockIdx.x * 2048 + ((tid * 16) & 2047);

    auto fill = [&](int j) {
        const int st = j & (STAGES - 1);
        const uint32_t aS = sbase + st * (STAGE_FLOATS * 4);
        const uint32_t bS = aS + A_STAGE_FLOATS * 4;
        const float* arow = ((j < 32) ? x : h) + (size_t)(m0 + a_row) * DH + (j & 31) * BK;
        cp16(aS + (a_row * AROWSTRIDE + a_c0 * 4) * 4,       arow + a_c0 * 4);
        cp16(aS + (a_row * AROWSTRIDE + (a_c0 + 1) * 4) * 4, arow + (a_c0 + 1) * 4);
        const float* bsrc = g_Wp + (size_t)(2 * j + b_ks) * 16384 + b_goff;
        const uint32_t bd = bS + tid * 64;
#pragma unroll
        for (int c = 0; c < 4; c++) cp16(bd + c * 16, bsrc + c * 4);
    };

    auto compute = [&](int st) {
        const float* A  = smem + st * STAGE_FLOATS
                               + (warp_m * 64 + (lane >> 2)) * AROWSTRIDE + (lane & 3);
        const float* Bm = smem + st * STAGE_FLOATS + A_STAGE_FLOATS
                               + warp_n * 512 + lane * 2;
#pragma unroll
        for (int ks = 0; ks < 2; ks++) {
            uint32_t af[4][4];
            uint2 bf[8];
#pragma unroll
            for (int mi = 0; mi < 4; mi++) {
                const float* p = A + mi * (16 * AROWSTRIDE) + ks * 8;
                af[mi][0] = __float_as_uint(tf32r(p[0]));
                af[mi][1] = __float_as_uint(tf32r(p[8 * AROWSTRIDE]));
                af[mi][2] = __float_as_uint(tf32r(p[4]));
                af[mi][3] = __float_as_uint(tf32r(p[8 * AROWSTRIDE + 4]));
            }
#pragma unroll
            for (int ni = 0; ni < 8; ni++)
                bf[ni] = *(const uint2*)&Bm[ks * 2048 + ni * 64];
#pragma unroll
            for (int mi = 0; mi < 4; mi++)
#pragma unroll
                for (int ni = 0; ni < 8; ni++)
                    asm volatile(
                        "mma.sync.aligned.m16n8k8.row.col.f32.tf32.tf32.f32 "
                        "{%0,%1,%2,%3},{%4,%5,%6,%7},{%8,%9},{%0,%1,%2,%3};"
                        : "+f"(acc[mi][ni][0]), "+f"(acc[mi][ni][1]),
                          "+f"(acc[mi][ni][2]), "+f"(acc[mi][ni][3])
                        : "r"(af[mi][0]), "r"(af[mi][1]), "r"(af[mi][2]), "r"(af[mi][3]),
                          "r"(bf[ni].x), "r"(bf[ni].y));
        }
    };

    // ---- pipelined mainloop: one sync per k-tile ----
    fill(0); cp_commit();
    fill(1); cp_commit();
    fill(2); cp_commit();
#pragma unroll 1
    for (int kb = 0; kb < NKB; kb++) {
        cp_wait<2>();            // group kb complete for this thread
        __syncthreads();         // all threads' stage-kb data visible; compute(kb-1) done
        if (kb + 3 < NKB) fill(kb + 3);   // overwrites slot (kb-1)&3 — safe after sync
        cp_commit();             // keep group numbering aligned (empty group near tail)
        compute(kb & 3);
    }

    // ---- fused gate epilogue (single pass through smem) ----
    __syncthreads();
    {
        const int rl = warp_m * 64 + (lane >> 2);
        const int cl = warp_n * 64 + 2 * (lane & 3);
#pragma unroll
        for (int mi = 0; mi < 4; mi++)
#pragma unroll
            for (int ni = 0; ni < 8; ni++) {
                float* p = smem + (rl + mi * 16) * EST + cl + ni * 8;
                *(float2*)&p[0]       = make_float2(acc[mi][ni][0], acc[mi][ni][1]);
                *(float2*)&p[8 * EST] = make_float2(acc[mi][ni][2], acc[mi][ni][3]);
            }
    }
    __syncthreads();

#pragma unroll 1
    for (int it = 0; it < 32; it++) {
        const int idx = it * 256 + tid;       // 0..8191
        const int row = idx >> 6;             // 0..127
        const int u   = idx & 63;             // unit within tile
        const int grow = m0 + row;
        const int hid  = (n0 >> 2) + u;
        float4 z = *(const float4*)&smem[row * EST + 4 * u];
        float4 b = *(const float4*)&g_bp[n0 + 4 * u];
        float iv = sig_fast(z.x + b.x);
        float fv = sig_fast(z.y + b.y);
        float ov = sig_fast(z.z + b.z);
        float gv = tanh_fast(z.w + b.w);
        float Cn = fv * Cin[(size_t)grow * DH + hid] + iv * gv;
        float hn = ov * tanh_fast(Cn);
        out[(size_t)grow * DH + hid]                   = Cn;
        out[(size_t)NB * DH + (size_t)grow * DH + hid] = hn;
    }
}

extern "C" void kernel_launch(void* const* d_in, const int* in_sizes, int n_in,
                              void* d_out, int out_size) {
    const float* x  = (const float*)d_in[0];
    const float* C  = (const float*)d_in[1];
    const float* h  = (const float*)d_in[2];
    const float* Wx = (const float*)d_in[3];
    const float* bx = (const float*)d_in[4];
    const float* Wh = (const float*)d_in[5];
    const float* bh = (const float*)d_in[6];

    prep_kernel<<<(FOURH * KTOT + 255) / 256, 256>>>(Wx, Wh, bx, bh);

    static int smem_set = 0;
    if (!smem_set) {
        cudaFuncSetAttribute(lstm_kernel, cudaFuncAttributeMaxDynamicSharedMemorySize, DYN_SMEM);
        smem_set = 1;
    }
    dim3 grid(FOURH / BN, NB / BM);   // (8, 256) — x-fastest: A panel reused in L2
    lstm_kernel<<<grid, 256, DYN_SMEM>>>(x, h, C, (float*)d_out);
}

// round 6
// speedup vs baseline: 1.0701x; 1.0624x over previous
#include <cuda_runtime.h>
#include <cstdint>

// LSTMCell fused: z = [x|h] @ Wp + bp ; gates -> C_new, h_new
// GEMM [32768 x 1024] * [1024 x 2048], mma.sync tf32 m16n8k8.
// R6: two INDEPENDENT 128-thread CTAs per SM (CTA tile 128x128, warp tile
// 64x64). One warp per SMSP per CTA -> when one CTA stalls on its barrier /
// cp.async wait, the co-resident CTA keeps the tensor pipe busy.

#define NB    32768
#define DH    512
#define FOURH 2048
#define KTOT  1024
#define NKB   64          // KTOT / BK

#define BM 128
#define BN 128
#define BK 16
#define STAGES 4

#define AROWSTRIDE 20                        // 16 data + 4 pad floats; conflict-free
#define A_STAGE_FLOATS (BM * AROWSTRIDE)     // 2560
#define B_STAGE_FLOATS (BN * BK)             // 2048
#define STAGE_FLOATS   (A_STAGE_FLOATS + B_STAGE_FLOATS)  // 4608
#define DYN_SMEM       (STAGES * STAGE_FLOATS * 4)        // 73728 B -> 2 CTAs/SM
#define EST 132                              // epilogue stride: 128*132*4 = 67.6KB

__device__ float g_Wp[(size_t)FOURH * KTOT]; // fragment-linear tiled B^T (validated)
__device__ float g_bp[FOURH];                // combined gate-interleaved bias

__device__ __forceinline__ float tf32r(float x) {
    float r; asm("cvt.rna.tf32.f32 %0, %1;" : "=f"(r) : "f"(x)); return r;
}
__device__ __forceinline__ float tanh_fast(float x) {
    float r; asm("tanh.approx.f32 %0, %1;" : "=f"(r) : "f"(x)); return r;
}
__device__ __forceinline__ float sig_fast(float x) { return 0.5f * tanh_fast(0.5f * x) + 0.5f; }

__device__ __forceinline__ void cp16(uint32_t dst, const float* src) {
    asm volatile("cp.async.cg.shared.global [%0], [%1], 16;" :: "r"(dst), "l"(src));
}
__device__ __forceinline__ void cp_commit() { asm volatile("cp.async.commit_group;" ::: "memory"); }
template <int N> __device__ __forceinline__ void cp_wait() {
    asm volatile("cp.async.wait_group %0;" :: "n"(N) : "memory");
}
__device__ __forceinline__ uint32_t smem_u32(const void* p) {
    uint32_t a;
    asm("{ .reg .u64 t; cvta.to.shared.u64 t, %1; cvt.u32.u64 %0, t; }" : "=r"(a) : "l"(p));
    return a;
}

// ---------------- prep (unchanged, validated) ----------------
// B^T element (n, k): n gate-interleaved (j=n>>2, g=n&3), tf32-RNA rounded.
// Fragment-linear: tile (kb8=k>>3, nb=n>>3) of 64 floats at
//   ((kb8*256 + nb)*64) + (n_in*4 + (k_in&3))*2 + (k_in>>2)
__global__ void prep_kernel(const float* __restrict__ Wx, const float* __restrict__ Wh,
                            const float* __restrict__ bx, const float* __restrict__ bh) {
    int idx = blockIdx.x * 256 + threadIdx.x;
    if (idx < FOURH * KTOT) {
        int kb8  = idx >> 14;
        int nb   = (idx >> 6) & 255;
        int pos  = idx & 63;
        int jbit = pos & 1;
        int t    = pos >> 1;
        int n_in = t >> 2;
        int k_in = (t & 3) | (jbit << 2);
        int n = nb * 8 + n_in;
        int k = kb8 * 8 + k_in;
        int j = n >> 2, g = n & 3;
        float v = (k < DH) ? Wx[k * FOURH + g * DH + j]
                           : Wh[(k - DH) * FOURH + g * DH + j];
        g_Wp[idx] = tf32r(v);
    }
    if (idx < FOURH) {
        int j = idx >> 2, g = idx & 3;
        g_bp[idx] = bx[g * DH + j] + bh[g * DH + j];
    }
}

// ---------------- main kernel ----------------
__global__ void __launch_bounds__(128, 2)
lstm_kernel(const float* __restrict__ x, const float* __restrict__ h,
            const float* __restrict__ Cin, float* __restrict__ out) {
    extern __shared__ float smem[];

    const int tid    = threadIdx.x;
    const int lane   = tid & 31;
    const int wid    = tid >> 5;        // 0..3
    const int warp_m = wid & 1;         // 0..1 : 64-row halves
    const int warp_n = wid >> 1;        // 0..1 : 64-col halves
    const int m0 = blockIdx.y * BM;
    const int n0 = blockIdx.x * BN;

    float acc[4][8][4];
#pragma unroll
    for (int a = 0; a < 4; a++)
#pragma unroll
        for (int b = 0; b < 8; b++)
#pragma unroll
            for (int c = 0; c < 4; c++) acc[a][b][c] = 0.f;

    const uint32_t sbase = smem_u32(smem);

    // ---- fill geometry ----
    // A: thread t copies row t (16 floats = 4 cp16), conflict-free per 8-lane phase.
    // B: thread t copies 4 x 16B chunks at chunk ids {c*128 + t} (contiguous phases).
    uint32_t b_soff[4];
    uint32_t b_goff[4];
#pragma unroll
    for (int c = 0; c < 4; c++) {
        int idx = c * 512 + tid * 4;             // float index within 2048-float stage
        b_soff[c] = (uint32_t)((c * 128 + tid) * 16);
        b_goff[c] = (uint32_t)(((idx >> 10) * 16384) + (idx & 1023));
    }

    auto fill = [&](int j) {
        const int st = j & (STAGES - 1);
        const uint32_t aS = sbase + st * (STAGE_FLOATS * 4);
        const uint32_t bS = aS + A_STAGE_FLOATS * 4;
        const float* arow = ((j < 32) ? x : h) + (size_t)(m0 + tid) * DH + (j & 31) * BK;
#pragma unroll
        for (int c = 0; c < 4; c++)
            cp16(aS + (tid * AROWSTRIDE + c * 4) * 4, arow + c * 4);
        const float* bbase = g_Wp + (size_t)(2 * j) * 16384 + (size_t)blockIdx.x * 1024;
#pragma unroll
        for (int c = 0; c < 4; c++)
            cp16(bS + b_soff[c], bbase + b_goff[c]);
    };

    auto compute = [&](int st) {
        const float* A  = smem + st * STAGE_FLOATS
                               + (warp_m * 64 + (lane >> 2)) * AROWSTRIDE + (lane & 3);
        const float* Bm = smem + st * STAGE_FLOATS + A_STAGE_FLOATS
                               + warp_n * 512 + lane * 2;
#pragma unroll
        for (int ks = 0; ks < 2; ks++) {
            uint32_t af[4][4];
            uint2 bf[8];
#pragma unroll
            for (int mi = 0; mi < 4; mi++) {
                const float* p = A + mi * (16 * AROWSTRIDE) + ks * 8;
                af[mi][0] = __float_as_uint(tf32r(p[0]));
                af[mi][1] = __float_as_uint(tf32r(p[8 * AROWSTRIDE]));
                af[mi][2] = __float_as_uint(tf32r(p[4]));
                af[mi][3] = __float_as_uint(tf32r(p[8 * AROWSTRIDE + 4]));
            }
#pragma unroll
            for (int ni = 0; ni < 8; ni++)
                bf[ni] = *(const uint2*)&Bm[ks * 1024 + ni * 64];
#pragma unroll
            for (int mi = 0; mi < 4; mi++)
#pragma unroll
                for (int ni = 0; ni < 8; ni++)
                    asm volatile(
                        "mma.sync.aligned.m16n8k8.row.col.f32.tf32.tf32.f32 "
                        "{%0,%1,%2,%3},{%4,%5,%6,%7},{%8,%9},{%0,%1,%2,%3};"
                        : "+f"(acc[mi][ni][0]), "+f"(acc[mi][ni][1]),
                          "+f"(acc[mi][ni][2]), "+f"(acc[mi][ni][3])
                        : "r"(af[mi][0]), "r"(af[mi][1]), "r"(af[mi][2]), "r"(af[mi][3]),
                          "r"(bf[ni].x), "r"(bf[ni].y));
        }
    };

    // ---- pipelined mainloop: one barrier per k-tile (4 warps, cheap) ----
    fill(0); cp_commit();
    fill(1); cp_commit();
    fill(2); cp_commit();
#pragma unroll 1
    for (int kb = 0; kb < NKB; kb++) {
        cp_wait<2>();            // own group kb complete
        __syncthreads();         // all threads' stage-kb data visible
        if (kb + 3 < NKB) fill(kb + 3);   // overwrites slot (kb-1)&3 — safe after sync
        cp_commit();             // keep group numbering aligned
        compute(kb & 3);
    }

    // ---- fused gate epilogue (single pass through smem) ----
    __syncthreads();
    {
        const int rl = warp_m * 64 + (lane >> 2);
        const int cl = warp_n * 64 + 2 * (lane & 3);
#pragma unroll
        for (int mi = 0; mi < 4; mi++)
#pragma unroll
            for (int ni = 0; ni < 8; ni++) {
                float* p = smem + (rl + mi * 16) * EST + cl + ni * 8;
                *(float2*)&p[0]       = make_float2(acc[mi][ni][0], acc[mi][ni][1]);
                *(float2*)&p[8 * EST] = make_float2(acc[mi][ni][2], acc[mi][ni][3]);
            }
    }
    __syncthreads();

#pragma unroll 1
    for (int it = 0; it < 32; it++) {
        const int idx = it * 128 + tid;       // 0..4095
        const int row = idx >> 5;             // 0..127
        const int u   = idx & 31;             // hidden unit within tile
        const int grow = m0 + row;
        const int hid  = (n0 >> 2) + u;
        float4 z = *(const float4*)&smem[row * EST + 4 * u];
        float4 b = *(const float4*)&g_bp[n0 + 4 * u];
        float iv = sig_fast(z.x + b.x);
        float fv = sig_fast(z.y + b.y);
        float ov = sig_fast(z.z + b.z);
        float gv = tanh_fast(z.w + b.w);
        float Cn = fv * Cin[(size_t)grow * DH + hid] + iv * gv;
        float hn = ov * tanh_fast(Cn);
        out[(size_t)grow * DH + hid]                   = Cn;
        out[(size_t)NB * DH + (size_t)grow * DH + hid] = hn;
    }
}

extern "C" void kernel_launch(void* const* d_in, const int* in_sizes, int n_in,
                              void* d_out, int out_size) {
    const float* x  = (const float*)d_in[0];
    const float* C  = (const float*)d_in[1];
    const float* h  = (const float*)d_in[2];
    const float* Wx = (const float*)d_in[3];
    const float* bx = (const float*)d_in[4];
    const float* Wh = (const float*)d_in[5];
    const float* bh = (const float*)d_in[6];

    prep_kernel<<<(FOURH * KTOT + 255) / 256, 256>>>(Wx, Wh, bx, bh);

    cudaFuncSetAttribute(lstm_kernel, cudaFuncAttributeMaxDynamicSharedMemorySize, DYN_SMEM);
    dim3 grid(FOURH / BN, NB / BM);   // (16, 256) — x-fastest: A panel reused in L2
    lstm_kernel<<<grid, 128, DYN_SMEM>>>(x, h, C, (float*)d_out);
}